// round 1
// baseline (speedup 1.0000x reference)
#include <cuda_runtime.h>
#include <math.h>

#define BB 4
#define TT 2048
#define CC 1024
#define HS 64
#define ROWS (BB*TT)   // 8192

// scratch for q,k,v projections (allocation-free rule -> device globals)
__device__ float g_q[ROWS*HS];
__device__ float g_k[ROWS*HS];
__device__ float g_v[ROWS*HS];

// ---------------------------------------------------------------------------
// Kernel 1: QKV projection.  out[r][h] = sum_c x[r][c] * W[c][h]
// grid (ROWS/64, 3), block 256.  64x64 tile, BK=32, 4x4 micro-tile/thread.
// ---------------------------------------------------------------------------
__global__ void qkv_kernel(const float* __restrict__ x,
                           const float* __restrict__ Wq,
                           const float* __restrict__ Wk,
                           const float* __restrict__ Wv) {
    __shared__ float xs[64][32];
    __shared__ float ws[32][64];

    const float* W   = (blockIdx.y == 0) ? Wq  : (blockIdx.y == 1 ? Wk  : Wv);
    float*       out = (blockIdx.y == 0) ? g_q : (blockIdx.y == 1 ? g_k : g_v);

    const int row0 = blockIdx.x * 64;
    const int tid  = threadIdx.x;
    const int ty   = tid >> 4;     // 0..15
    const int tx   = tid & 15;     // 0..15

    float acc[4][4] = {};

    for (int k0 = 0; k0 < CC; k0 += 32) {
        // load x tile: 64x32 floats = 512 float4, 2 per thread
        #pragma unroll
        for (int i = 0; i < 2; i++) {
            int idx = tid + i * 256;             // 0..511
            int r   = idx >> 3;                  // /8 float4 per row
            int c4  = idx & 7;
            float4 v = *(const float4*)(x + (size_t)(row0 + r) * CC + k0 + c4 * 4);
            *(float4*)&xs[r][c4 * 4] = v;
        }
        // load W tile: 32x64 floats = 512 float4, 2 per thread
        #pragma unroll
        for (int i = 0; i < 2; i++) {
            int idx = tid + i * 256;
            int r   = idx >> 4;                  // /16 float4 per row
            int c4  = idx & 15;
            float4 v = *(const float4*)(W + (size_t)(k0 + r) * HS + c4 * 4);
            *(float4*)&ws[r][c4 * 4] = v;
        }
        __syncthreads();

        #pragma unroll
        for (int kk = 0; kk < 32; kk++) {
            float a[4];
            #pragma unroll
            for (int i = 0; i < 4; i++) a[i] = xs[ty * 4 + i][kk];
            float4 bv = *(float4*)&ws[kk][tx * 4];
            float b[4] = {bv.x, bv.y, bv.z, bv.w};
            #pragma unroll
            for (int i = 0; i < 4; i++)
                #pragma unroll
                for (int j = 0; j < 4; j++)
                    acc[i][j] = fmaf(a[i], b[j], acc[i][j]);
        }
        __syncthreads();
    }

    #pragma unroll
    for (int i = 0; i < 4; i++) {
        int r = row0 + ty * 4 + i;
        float4 v = make_float4(acc[i][0], acc[i][1], acc[i][2], acc[i][3]);
        *(float4*)(out + (size_t)r * HS + tx * 4) = v;
    }
}

// ---------------------------------------------------------------------------
// Kernel 2: causal flash attention, fp32, online softmax.
// grid (T/64, B), block 256, dynamic smem.
// Thread (ty,tx) in 16x16 grid owns a 4x4 micro-tile of the 64x64 S tile.
// Row reductions via shfl_xor within 16-lane groups.
// ---------------------------------------------------------------------------
__global__ void attn_kernel(float* __restrict__ out) {
    extern __shared__ float smem[];
    float* Qs = smem;             // 64*64
    float* Ks = Qs + 64 * 64;     // 64*65 (padded: K^T reads -> 2-way not 16-way)
    float* Vs = Ks + 64 * 65;     // 64*64
    float* Ps = Vs + 64 * 64;     // 64*64

    const int b   = blockIdx.y;
    const int qt  = blockIdx.x;
    const int tid = threadIdx.x;
    const int ty  = tid >> 4;
    const int tx  = tid & 15;

    const float scale = 0.03125f;  // 1/sqrt(C) = 1/32

    // load Q tile, pre-scaled
    const float* qptr = g_q + ((size_t)b * TT + qt * 64) * HS;
    #pragma unroll
    for (int i = 0; i < 4; i++) {
        int idx = tid + i * 256;             // 0..1023 (64 rows x 16 float4)
        int r   = idx >> 4;
        int c4  = idx & 15;
        float4 v = *(const float4*)(qptr + r * HS + c4 * 4);
        v.x *= scale; v.y *= scale; v.z *= scale; v.w *= scale;
        *(float4*)&Qs[r * 64 + c4 * 4] = v;
    }

    float acc[4][4] = {};
    float m[4], l[4];
    #pragma unroll
    for (int i = 0; i < 4; i++) { m[i] = -INFINITY; l[i] = 0.f; }

    for (int kt = 0; kt <= qt; kt++) {
        __syncthreads();   // previous iter's Vs/Ps reads done; Qs stores (iter 0)

        const float* kptr = g_k + ((size_t)b * TT + kt * 64) * HS;
        const float* vptr = g_v + ((size_t)b * TT + kt * 64) * HS;
        #pragma unroll
        for (int i = 0; i < 4; i++) {
            int idx = tid + i * 256;
            int r   = idx >> 4;
            int c4  = idx & 15;
            float4 kv = *(const float4*)(kptr + r * HS + c4 * 4);
            Ks[r * 65 + c4 * 4 + 0] = kv.x;
            Ks[r * 65 + c4 * 4 + 1] = kv.y;
            Ks[r * 65 + c4 * 4 + 2] = kv.z;
            Ks[r * 65 + c4 * 4 + 3] = kv.w;
            float4 vv = *(const float4*)(vptr + r * HS + c4 * 4);
            *(float4*)&Vs[r * 64 + c4 * 4] = vv;
        }
        __syncthreads();

        // S = Q K^T  (scale already folded into Q)
        float s[4][4] = {};
        #pragma unroll
        for (int h = 0; h < 64; h++) {
            float a[4], bb[4];
            #pragma unroll
            for (int i = 0; i < 4; i++) a[i]  = Qs[(ty * 4 + i) * 64 + h];
            #pragma unroll
            for (int j = 0; j < 4; j++) bb[j] = Ks[(tx * 4 + j) * 65 + h];
            #pragma unroll
            for (int i = 0; i < 4; i++)
                #pragma unroll
                for (int j = 0; j < 4; j++)
                    s[i][j] = fmaf(a[i], bb[j], s[i][j]);
        }

        // causal mask on the diagonal tile
        if (kt == qt) {
            #pragma unroll
            for (int i = 0; i < 4; i++)
                #pragma unroll
                for (int j = 0; j < 4; j++)
                    if (tx * 4 + j > ty * 4 + i) s[i][j] = -INFINITY;
        }

        // row max (thread-local over 4 cols, then 16-lane shuffle)
        float mt[4];
        #pragma unroll
        for (int i = 0; i < 4; i++) {
            float v = fmaxf(fmaxf(s[i][0], s[i][1]), fmaxf(s[i][2], s[i][3]));
            #pragma unroll
            for (int o = 8; o >= 1; o >>= 1)
                v = fmaxf(v, __shfl_xor_sync(0xffffffffu, v, o));
            mt[i] = v;
        }

        float mn[4], alpha[4];
        #pragma unroll
        for (int i = 0; i < 4; i++) {
            mn[i]    = fmaxf(m[i], mt[i]);
            alpha[i] = __expf(m[i] - mn[i]);
            m[i]     = mn[i];
        }

        // p = exp(s - m_new), stage to smem, accumulate row sums
        float rs[4];
        #pragma unroll
        for (int i = 0; i < 4; i++) {
            float p0 = __expf(s[i][0] - mn[i]);
            float p1 = __expf(s[i][1] - mn[i]);
            float p2 = __expf(s[i][2] - mn[i]);
            float p3 = __expf(s[i][3] - mn[i]);
            float4 pv = make_float4(p0, p1, p2, p3);
            *(float4*)&Ps[(ty * 4 + i) * 64 + tx * 4] = pv;
            float v = (p0 + p1) + (p2 + p3);
            #pragma unroll
            for (int o = 8; o >= 1; o >>= 1)
                v += __shfl_xor_sync(0xffffffffu, v, o);
            rs[i] = v;
        }

        #pragma unroll
        for (int i = 0; i < 4; i++) {
            l[i] = l[i] * alpha[i] + rs[i];
            #pragma unroll
            for (int j = 0; j < 4; j++) acc[i][j] *= alpha[i];
        }
        __syncthreads();

        // acc += Ps @ Vs
        #pragma unroll
        for (int j = 0; j < 64; j++) {
            float a[4];
            #pragma unroll
            for (int i = 0; i < 4; i++) a[i] = Ps[(ty * 4 + i) * 64 + j];
            float4 bv = *(float4*)&Vs[j * 64 + tx * 4];
            float bb[4] = {bv.x, bv.y, bv.z, bv.w};
            #pragma unroll
            for (int i = 0; i < 4; i++)
                #pragma unroll
                for (int jj = 0; jj < 4; jj++)
                    acc[i][jj] = fmaf(a[i], bb[jj], acc[i][jj]);
        }
    }

    // epilogue: normalize and write out [B,T,HS]
    #pragma unroll
    for (int i = 0; i < 4; i++) {
        float inv = 1.0f / l[i];
        int gr = qt * 64 + ty * 4 + i;
        float4 v = make_float4(acc[i][0] * inv, acc[i][1] * inv,
                               acc[i][2] * inv, acc[i][3] * inv);
        *(float4*)(out + ((size_t)b * TT + gr) * HS + tx * 4) = v;
    }
}

// ---------------------------------------------------------------------------
extern "C" void kernel_launch(void* const* d_in, const int* in_sizes, int n_in,
                              void* d_out, int out_size) {
    const float* x  = (const float*)d_in[0];
    const float* Wq = (const float*)d_in[1];
    const float* Wk = (const float*)d_in[2];
    const float* Wv = (const float*)d_in[3];
    float* out = (float*)d_out;

    qkv_kernel<<<dim3(ROWS / 64, 3), 256>>>(x, Wq, Wk, Wv);

    size_t smem_bytes = (size_t)(64 * 64 + 64 * 65 + 64 * 64 + 64 * 64) * sizeof(float);
    cudaFuncSetAttribute(attn_kernel,
                         cudaFuncAttributeMaxDynamicSharedMemorySize,
                         (int)smem_bytes);
    attn_kernel<<<dim3(TT / 64, BB), 256, smem_bytes>>>(out);
}

// round 3
// speedup vs baseline: 1.1875x; 1.1875x over previous
#include <cuda_runtime.h>
#include <math.h>
#include <stdint.h>

#define BB 4
#define TT 2048
#define CC 1024
#define HS 64
#define ROWS (BB*TT)   // 8192

__device__ float g_q[ROWS*HS];
__device__ float g_k[ROWS*HS];
__device__ float g_v[ROWS*HS];

// ---------------------------------------------------------------------------
// packed f32x2 helpers (B300 doubled-FP32 path; ptxas never emits these).
// NOTE: must use separate "=l" output + 3 inputs; "+l" tying ICEs nvcc.
// ---------------------------------------------------------------------------
union F2U { float2 f; unsigned long long u; };

__device__ __forceinline__ float2 ffma2(float2 a, float2 b, float2 c) {
    F2U A, B, C, D; A.f = a; B.f = b; C.f = c;
    asm("fma.rn.f32x2 %0, %1, %2, %3;" : "=l"(D.u) : "l"(A.u), "l"(B.u), "l"(C.u));
    return D.f;
}
__device__ __forceinline__ float2 fmul2(float2 a, float2 b) {
    F2U A, B, D; A.f = a; B.f = b;
    asm("mul.rn.f32x2 %0, %1, %2;" : "=l"(D.u) : "l"(A.u), "l"(B.u));
    return D.f;
}

// cp.async helpers
__device__ __forceinline__ void cp16(void* s, const void* g) {
    uint32_t sa = (uint32_t)__cvta_generic_to_shared(s);
    asm volatile("cp.async.cg.shared.global [%0], [%1], 16;" :: "r"(sa), "l"(g) : "memory");
}
__device__ __forceinline__ void cp_commit() { asm volatile("cp.async.commit_group;" ::: "memory"); }
template<int N> __device__ __forceinline__ void cp_wait() { asm volatile("cp.async.wait_group %0;" :: "n"(N) : "memory"); }

// ---------------------------------------------------------------------------
// Kernel 1: fused QKV projection. One pass over x, 64x192 tile, BK=16,
// double-buffered cp.async, FFMA2 inner loop.  grid 128, block 256.
// ---------------------------------------------------------------------------
__global__ void __launch_bounds__(256) qkv_kernel(const float* __restrict__ x,
                                                  const float* __restrict__ Wq,
                                                  const float* __restrict__ Wk,
                                                  const float* __restrict__ Wv) {
    __shared__ float xs[2][64][16];    // 2 x 4KB
    __shared__ float ws[2][16][192];   // 2 x 12KB

    const int tid  = threadIdx.x;
    const int ty   = tid >> 4;   // 0..15
    const int tx   = tid & 15;   // 0..15
    const int row0 = blockIdx.x * 64;

    // x-tile loader: 64x16 floats = 256 float4, 1 per thread
    const int xr  = tid >> 2;
    const int xc  = (tid & 3) * 4;
    const float* xsrc = x + (size_t)(row0 + xr) * CC + xc;

    // w-tile loader: 16x192 floats = 768 float4, 3 per thread
    const float* Wsel[3] = {Wq, Wk, Wv};
    int wrow[3], wcol[3];
    const float* wsrc[3];
    #pragma unroll
    for (int i = 0; i < 3; i++) {
        int idx = tid + i * 256;          // 0..767
        int wr  = idx / 48;               // 0..15
        int wc  = idx % 48;               // float4 col 0..47
        wrow[i] = wr; wcol[i] = wc * 4;
        wsrc[i] = Wsel[wc / 16] + (size_t)wr * HS + (wc % 16) * 4;
    }

    auto load = [&](int kb, int s) {
        cp16(&xs[s][xr][xc], xsrc + kb * 16);
        #pragma unroll
        for (int i = 0; i < 3; i++)
            cp16(&ws[s][wrow[i]][wcol[i]], wsrc[i] + (size_t)kb * 16 * HS);
        cp_commit();
    };

    float2 acc[4][6];
    #pragma unroll
    for (int i = 0; i < 4; i++)
        #pragma unroll
        for (int j = 0; j < 6; j++) acc[i][j] = make_float2(0.f, 0.f);

    load(0, 0);
    for (int kb = 0; kb < CC / 16; kb++) {
        const int buf = kb & 1;
        if (kb + 1 < CC / 16) { load(kb + 1, buf ^ 1); cp_wait<1>(); }
        else                  { cp_wait<0>(); }
        __syncthreads();

        #pragma unroll
        for (int kk = 0; kk < 16; kk++) {
            float2 asp[4];
            #pragma unroll
            for (int i = 0; i < 4; i++) {
                float a = xs[buf][ty * 4 + i][kk];
                asp[i] = make_float2(a, a);
            }
            #pragma unroll
            for (int s = 0; s < 3; s++) {
                float4 bv = *(const float4*)&ws[buf][kk][s * 64 + tx * 4];
                float2 b0 = make_float2(bv.x, bv.y);
                float2 b1 = make_float2(bv.z, bv.w);
                #pragma unroll
                for (int i = 0; i < 4; i++) {
                    acc[i][2*s]   = ffma2(asp[i], b0, acc[i][2*s]);
                    acc[i][2*s+1] = ffma2(asp[i], b1, acc[i][2*s+1]);
                }
            }
        }
        __syncthreads();
    }

    float* outs[3] = {g_q, g_k, g_v};
    #pragma unroll
    for (int s = 0; s < 3; s++)
        #pragma unroll
        for (int i = 0; i < 4; i++) {
            float4 v = make_float4(acc[i][2*s].x, acc[i][2*s].y,
                                   acc[i][2*s+1].x, acc[i][2*s+1].y);
            *(float4*)(outs[s] + (size_t)(row0 + ty * 4 + i) * HS + tx * 4) = v;
        }
}

// ---------------------------------------------------------------------------
// Kernel 2: balanced causal flash attention.
// BM=32, BN=64. Block p handles q-tiles {p, 63-p} -> exactly 33 k-iters/block.
// K transposed in smem (FFMA2-friendly), V via cp.async, double buffered.
// grid (32, B), block 256.
// ---------------------------------------------------------------------------
__global__ void __launch_bounds__(256) attn_kernel(float* __restrict__ out) {
    extern __shared__ float sm[];
    float* Qs = sm;                  // 32*64
    float* Kt = Qs + 32 * 64;        // 2 * 64*64  (Kt[h][n], n contiguous)
    float* Vs = Kt + 2 * 64 * 64;    // 2 * 64*64
    float* Ps = Vs + 2 * 64 * 64;    // 32*64

    const int b    = blockIdx.y;
    const int p    = blockIdx.x;
    const int tid  = threadIdx.x;
    const int ty   = tid >> 4;       // 0..15 -> 2 rows each
    const int tx   = tid & 15;       // 0..15 -> 4 cols each
    const int lane = tid & 31;
    const int warp = tid >> 5;
    const float scale = 0.03125f;    // 1/sqrt(C)

    const float* qbase = g_q + (size_t)b * TT * HS;
    const float* kbase = g_k + (size_t)b * TT * HS;
    const float* vbase = g_v + (size_t)b * TT * HS;

    // K transpose-loader mapping: each thread loads 4 float4 and scatters
    const int kr  = (warp & 1) * 32 + lane;  // source row 0..63
    const int kc4 = (warp >> 1) * 4;         // float4-col base (x4 -> h0)

    #pragma unroll 1
    for (int pass = 0; pass < 2; pass++) {
        const int qt  = pass ? (63 - p) : p;
        const int nkt = (qt * 32 + 31) / 64 + 1;

        __syncthreads();  // previous pass done with all smem

        // load Q tile (pre-scaled): 32x64 = 512 float4, 2/thread
        {
            const float* qp = qbase + (size_t)qt * 32 * HS;
            #pragma unroll
            for (int i = 0; i < 2; i++) {
                int idx = tid + i * 256;
                int r = idx >> 4, c = (idx & 15) * 4;
                float4 v = *(const float4*)(qp + r * HS + c);
                v.x *= scale; v.y *= scale; v.z *= scale; v.w *= scale;
                *(float4*)&Qs[r * 64 + c] = v;
            }
        }
        // prologue: tile 0 -> buffer 0
        {
            #pragma unroll
            for (int i = 0; i < 4; i++) {
                int idx = tid + i * 256;
                int r = idx >> 4, c = (idx & 15) * 4;
                cp16(&Vs[r * 64 + c], vbase + r * HS + c);
            }
            cp_commit();
            float4 kv[4];
            #pragma unroll
            for (int i = 0; i < 4; i++)
                kv[i] = *(const float4*)(kbase + kr * HS + (kc4 + i) * 4);
            #pragma unroll
            for (int i = 0; i < 4; i++) {
                int h0 = (kc4 + i) * 4;
                Kt[(h0+0)*64 + kr] = kv[i].x;
                Kt[(h0+1)*64 + kr] = kv[i].y;
                Kt[(h0+2)*64 + kr] = kv[i].z;
                Kt[(h0+3)*64 + kr] = kv[i].w;
            }
            cp_wait<0>();
        }
        __syncthreads();

        float2 acc[2][2];
        #pragma unroll
        for (int i = 0; i < 2; i++) { acc[i][0] = make_float2(0,0); acc[i][1] = make_float2(0,0); }
        float m[2] = {-INFINITY, -INFINITY};
        float l[2] = {0.f, 0.f};

        for (int kt = 0; kt < nkt; kt++) {
            const int buf = kt & 1;
            const bool pf = (kt + 1 < nkt);
            float4 kv[4];
            if (pf) {
                const float* vp = vbase + (size_t)(kt + 1) * 64 * HS;
                #pragma unroll
                for (int i = 0; i < 4; i++) {
                    int idx = tid + i * 256;
                    int r = idx >> 4, c = (idx & 15) * 4;
                    cp16(&Vs[(buf ^ 1) * 4096 + r * 64 + c], vp + r * HS + c);
                }
                cp_commit();
                const float* kp = kbase + (size_t)(kt + 1) * 64 * HS;
                #pragma unroll
                for (int i = 0; i < 4; i++)
                    kv[i] = *(const float4*)(kp + kr * HS + (kc4 + i) * 4);
            }

            // ---- S = Q K^T (scale folded into Q) ----
            float2 s2[2][2];
            #pragma unroll
            for (int i = 0; i < 2; i++) { s2[i][0] = make_float2(0,0); s2[i][1] = make_float2(0,0); }
            const float* KtB = Kt + buf * 4096;
            #pragma unroll 8
            for (int h = 0; h < 64; h++) {
                float a0 = Qs[(ty*2+0)*64 + h];
                float a1 = Qs[(ty*2+1)*64 + h];
                float2 b0 = *(const float2*)&KtB[h * 64 + tx * 4];
                float2 b1 = *(const float2*)&KtB[h * 64 + tx * 4 + 2];
                float2 A0 = make_float2(a0, a0), A1 = make_float2(a1, a1);
                s2[0][0] = ffma2(A0, b0, s2[0][0]);
                s2[0][1] = ffma2(A0, b1, s2[0][1]);
                s2[1][0] = ffma2(A1, b0, s2[1][0]);
                s2[1][1] = ffma2(A1, b1, s2[1][1]);
            }
            float s[2][4] = {{s2[0][0].x, s2[0][0].y, s2[0][1].x, s2[0][1].y},
                             {s2[1][0].x, s2[1][0].y, s2[1][1].x, s2[1][1].y}};

            if (kt == nkt - 1) {  // diagonal tile mask
                #pragma unroll
                for (int i = 0; i < 2; i++) {
                    int grow = qt * 32 + ty * 2 + i;
                    #pragma unroll
                    for (int j = 0; j < 4; j++)
                        if (kt * 64 + tx * 4 + j > grow) s[i][j] = -INFINITY;
                }
            }

            // ---- online softmax (row reductions over 16 lanes) ----
            #pragma unroll
            for (int i = 0; i < 2; i++) {
                float mt = fmaxf(fmaxf(s[i][0], s[i][1]), fmaxf(s[i][2], s[i][3]));
                #pragma unroll
                for (int o = 8; o >= 1; o >>= 1)
                    mt = fmaxf(mt, __shfl_xor_sync(0xffffffffu, mt, o));
                float mn = fmaxf(m[i], mt);
                float alpha = __expf(m[i] - mn);
                m[i] = mn;
                float p0 = __expf(s[i][0]-mn), p1 = __expf(s[i][1]-mn);
                float p2 = __expf(s[i][2]-mn), p3 = __expf(s[i][3]-mn);
                *(float4*)&Ps[(ty*2+i)*64 + tx*4] = make_float4(p0, p1, p2, p3);
                float rs = (p0 + p1) + (p2 + p3);
                #pragma unroll
                for (int o = 8; o >= 1; o >>= 1)
                    rs += __shfl_xor_sync(0xffffffffu, rs, o);
                l[i] = l[i] * alpha + rs;
                float2 al = make_float2(alpha, alpha);
                acc[i][0] = fmul2(acc[i][0], al);
                acc[i][1] = fmul2(acc[i][1], al);
            }
            __syncwarp();   // Ps rows live entirely within this warp

            // ---- acc += P V ----
            const float* VsB = Vs + buf * 4096;
            #pragma unroll 8
            for (int j = 0; j < 64; j++) {
                float a0 = Ps[(ty*2+0)*64 + j];
                float a1 = Ps[(ty*2+1)*64 + j];
                float4 bv = *(const float4*)&VsB[j * 64 + tx * 4];
                float2 b0 = make_float2(bv.x, bv.y), b1 = make_float2(bv.z, bv.w);
                float2 A0 = make_float2(a0, a0), A1 = make_float2(a1, a1);
                acc[0][0] = ffma2(A0, b0, acc[0][0]);
                acc[0][1] = ffma2(A0, b1, acc[0][1]);
                acc[1][0] = ffma2(A1, b0, acc[1][0]);
                acc[1][1] = ffma2(A1, b1, acc[1][1]);
            }
            __syncwarp();

            __syncthreads();   // all warps done reading buf
            if (pf) {
                float* KtN = Kt + (buf ^ 1) * 4096;
                #pragma unroll
                for (int i = 0; i < 4; i++) {
                    int h0 = (kc4 + i) * 4;
                    KtN[(h0+0)*64 + kr] = kv[i].x;
                    KtN[(h0+1)*64 + kr] = kv[i].y;
                    KtN[(h0+2)*64 + kr] = kv[i].z;
                    KtN[(h0+3)*64 + kr] = kv[i].w;
                }
                cp_wait<0>();
                __syncthreads();   // next buffer ready
            }
        }

        // epilogue
        #pragma unroll
        for (int i = 0; i < 2; i++) {
            float inv = 1.0f / l[i];
            int grow = qt * 32 + ty * 2 + i;
            float4 v = make_float4(acc[i][0].x * inv, acc[i][0].y * inv,
                                   acc[i][1].x * inv, acc[i][1].y * inv);
            *(float4*)(out + ((size_t)b * TT + grow) * HS + tx * 4) = v;
        }
    }
}

// ---------------------------------------------------------------------------
extern "C" void kernel_launch(void* const* d_in, const int* in_sizes, int n_in,
                              void* d_out, int out_size) {
    const float* x  = (const float*)d_in[0];
    const float* Wq = (const float*)d_in[1];
    const float* Wk = (const float*)d_in[2];
    const float* Wv = (const float*)d_in[3];
    float* out = (float*)d_out;

    qkv_kernel<<<ROWS / 64, 256>>>(x, Wq, Wk, Wv);

    size_t smem_bytes = (size_t)(32*64 + 2*64*64 + 2*64*64 + 32*64) * sizeof(float); // 80 KB
    cudaFuncSetAttribute(attn_kernel,
                         cudaFuncAttributeMaxDynamicSharedMemorySize,
                         (int)smem_bytes);
    attn_kernel<<<dim3(32, BB), 256, smem_bytes>>>(out);
}

// round 4
// speedup vs baseline: 1.1996x; 1.0102x over previous
#include <cuda_runtime.h>
#include <math.h>
#include <stdint.h>

#define BB 4
#define TT 2048
#define CC 1024
#define HS 64
#define ROWS (BB*TT)   // 8192

__device__ float g_q[ROWS*HS];
__device__ float g_k[ROWS*HS];
__device__ float g_v[ROWS*HS];

// ---------------------------------------------------------------------------
// packed f32x2 helpers (B300 doubled-FP32 path; ptxas never emits these).
// NOTE: must use separate "=l" output + 3 inputs; "+l" tying ICEs nvcc.
// ---------------------------------------------------------------------------
union F2U { float2 f; unsigned long long u; };

__device__ __forceinline__ float2 ffma2(float2 a, float2 b, float2 c) {
    F2U A, B, C, D; A.f = a; B.f = b; C.f = c;
    asm("fma.rn.f32x2 %0, %1, %2, %3;" : "=l"(D.u) : "l"(A.u), "l"(B.u), "l"(C.u));
    return D.f;
}
__device__ __forceinline__ float2 fmul2(float2 a, float2 b) {
    F2U A, B, D; A.f = a; B.f = b;
    asm("mul.rn.f32x2 %0, %1, %2;" : "=l"(D.u) : "l"(A.u), "l"(B.u));
    return D.f;
}

// cp.async helpers
__device__ __forceinline__ void cp16(void* s, const void* g) {
    uint32_t sa = (uint32_t)__cvta_generic_to_shared(s);
    asm volatile("cp.async.cg.shared.global [%0], [%1], 16;" :: "r"(sa), "l"(g) : "memory");
}
__device__ __forceinline__ void cp_commit() { asm volatile("cp.async.commit_group;" ::: "memory"); }
template<int N> __device__ __forceinline__ void cp_wait() { asm volatile("cp.async.wait_group %0;" :: "n"(N) : "memory"); }

// ---------------------------------------------------------------------------
// Kernel 1: fused QKV projection. One pass over x, 64x192 tile, BK=16,
// double-buffered cp.async, FFMA2 inner loop.  grid 128, block 256.
// ---------------------------------------------------------------------------
__global__ void __launch_bounds__(256) qkv_kernel(const float* __restrict__ x,
                                                  const float* __restrict__ Wq,
                                                  const float* __restrict__ Wk,
                                                  const float* __restrict__ Wv) {
    __shared__ float xs[2][64][16];    // 2 x 4KB
    __shared__ float ws[2][16][192];   // 2 x 12KB

    const int tid  = threadIdx.x;
    const int ty   = tid >> 4;   // 0..15
    const int tx   = tid & 15;   // 0..15
    const int row0 = blockIdx.x * 64;

    // x-tile loader: 64x16 floats = 256 float4, 1 per thread
    const int xr  = tid >> 2;
    const int xc  = (tid & 3) * 4;
    const float* xsrc = x + (size_t)(row0 + xr) * CC + xc;

    // w-tile loader: 16x192 floats = 768 float4, 3 per thread
    const float* Wsel[3] = {Wq, Wk, Wv};
    int wrow[3], wcol[3];
    const float* wsrc[3];
    #pragma unroll
    for (int i = 0; i < 3; i++) {
        int idx = tid + i * 256;          // 0..767
        int wr  = idx / 48;               // 0..15
        int wc  = idx % 48;               // float4 col 0..47
        wrow[i] = wr; wcol[i] = wc * 4;
        wsrc[i] = Wsel[wc / 16] + (size_t)wr * HS + (wc % 16) * 4;
    }

    auto load = [&](int kb, int s) {
        cp16(&xs[s][xr][xc], xsrc + kb * 16);
        #pragma unroll
        for (int i = 0; i < 3; i++)
            cp16(&ws[s][wrow[i]][wcol[i]], wsrc[i] + (size_t)kb * 16 * HS);
        cp_commit();
    };

    float2 acc[4][6];
    #pragma unroll
    for (int i = 0; i < 4; i++)
        #pragma unroll
        for (int j = 0; j < 6; j++) acc[i][j] = make_float2(0.f, 0.f);

    load(0, 0);
    for (int kb = 0; kb < CC / 16; kb++) {
        const int buf = kb & 1;
        if (kb + 1 < CC / 16) { load(kb + 1, buf ^ 1); cp_wait<1>(); }
        else                  { cp_wait<0>(); }
        __syncthreads();

        #pragma unroll
        for (int kk = 0; kk < 16; kk++) {
            float2 asp[4];
            #pragma unroll
            for (int i = 0; i < 4; i++) {
                float a = xs[buf][ty * 4 + i][kk];
                asp[i] = make_float2(a, a);
            }
            #pragma unroll
            for (int s = 0; s < 3; s++) {
                float4 bv = *(const float4*)&ws[buf][kk][s * 64 + tx * 4];
                float2 b0 = make_float2(bv.x, bv.y);
                float2 b1 = make_float2(bv.z, bv.w);
                #pragma unroll
                for (int i = 0; i < 4; i++) {
                    acc[i][2*s]   = ffma2(asp[i], b0, acc[i][2*s]);
                    acc[i][2*s+1] = ffma2(asp[i], b1, acc[i][2*s+1]);
                }
            }
        }
        __syncthreads();
    }

    float* outs[3] = {g_q, g_k, g_v};
    #pragma unroll
    for (int s = 0; s < 3; s++)
        #pragma unroll
        for (int i = 0; i < 4; i++) {
            float4 v = make_float4(acc[i][2*s].x, acc[i][2*s].y,
                                   acc[i][2*s+1].x, acc[i][2*s+1].y);
            *(float4*)(outs[s] + (size_t)(row0 + ty * 4 + i) * HS + tx * 4) = v;
        }
}

// ---------------------------------------------------------------------------
// Kernel 2: balanced causal flash attention.
// BM=32, BN=64. Block p handles q-tiles {p, 63-p} -> exactly 33 k-iters/block.
// K transposed in smem (FFMA2-friendly), V via cp.async, double buffered.
// grid (32, B), block 256.
// ---------------------------------------------------------------------------
__global__ void __launch_bounds__(256) attn_kernel(float* __restrict__ out) {
    extern __shared__ float sm[];
    float* Qs = sm;                  // 32*64
    float* Kt = Qs + 32 * 64;        // 2 * 64*64  (Kt[h][n], n contiguous)
    float* Vs = Kt + 2 * 64 * 64;    // 2 * 64*64
    float* Ps = Vs + 2 * 64 * 64;    // 32*64

    const int b    = blockIdx.y;
    const int p    = blockIdx.x;
    const int tid  = threadIdx.x;
    const int ty   = tid >> 4;       // 0..15 -> 2 rows each
    const int tx   = tid & 15;       // 0..15 -> 4 cols each
    const int lane = tid & 31;
    const int warp = tid >> 5;
    const float scale = 0.03125f;    // 1/sqrt(C)

    const float* qbase = g_q + (size_t)b * TT * HS;
    const float* kbase = g_k + (size_t)b * TT * HS;
    const float* vbase = g_v + (size_t)b * TT * HS;

    // K transpose-loader mapping: each thread loads 4 float4 and scatters
    const int kr  = (warp & 1) * 32 + lane;  // source row 0..63
    const int kc4 = (warp >> 1) * 4;         // float4-col base (x4 -> h0)

    #pragma unroll 1
    for (int pass = 0; pass < 2; pass++) {
        const int qt  = pass ? (63 - p) : p;
        const int nkt = (qt * 32 + 31) / 64 + 1;

        __syncthreads();  // previous pass done with all smem

        // load Q tile (pre-scaled): 32x64 = 512 float4, 2/thread
        {
            const float* qp = qbase + (size_t)qt * 32 * HS;
            #pragma unroll
            for (int i = 0; i < 2; i++) {
                int idx = tid + i * 256;
                int r = idx >> 4, c = (idx & 15) * 4;
                float4 v = *(const float4*)(qp + r * HS + c);
                v.x *= scale; v.y *= scale; v.z *= scale; v.w *= scale;
                *(float4*)&Qs[r * 64 + c] = v;
            }
        }
        // prologue: tile 0 -> buffer 0
        {
            #pragma unroll
            for (int i = 0; i < 4; i++) {
                int idx = tid + i * 256;
                int r = idx >> 4, c = (idx & 15) * 4;
                cp16(&Vs[r * 64 + c], vbase + r * HS + c);
            }
            cp_commit();
            float4 kv[4];
            #pragma unroll
            for (int i = 0; i < 4; i++)
                kv[i] = *(const float4*)(kbase + kr * HS + (kc4 + i) * 4);
            #pragma unroll
            for (int i = 0; i < 4; i++) {
                int h0 = (kc4 + i) * 4;
                Kt[(h0+0)*64 + kr] = kv[i].x;
                Kt[(h0+1)*64 + kr] = kv[i].y;
                Kt[(h0+2)*64 + kr] = kv[i].z;
                Kt[(h0+3)*64 + kr] = kv[i].w;
            }
            cp_wait<0>();
        }
        __syncthreads();

        float2 acc[2][2];
        #pragma unroll
        for (int i = 0; i < 2; i++) { acc[i][0] = make_float2(0,0); acc[i][1] = make_float2(0,0); }
        float m[2] = {-INFINITY, -INFINITY};
        float l[2] = {0.f, 0.f};

        for (int kt = 0; kt < nkt; kt++) {
            const int buf = kt & 1;
            const bool pf = (kt + 1 < nkt);
            float4 kv[4];
            if (pf) {
                const float* vp = vbase + (size_t)(kt + 1) * 64 * HS;
                #pragma unroll
                for (int i = 0; i < 4; i++) {
                    int idx = tid + i * 256;
                    int r = idx >> 4, c = (idx & 15) * 4;
                    cp16(&Vs[(buf ^ 1) * 4096 + r * 64 + c], vp + r * HS + c);
                }
                cp_commit();
                const float* kp = kbase + (size_t)(kt + 1) * 64 * HS;
                #pragma unroll
                for (int i = 0; i < 4; i++)
                    kv[i] = *(const float4*)(kp + kr * HS + (kc4 + i) * 4);
            }

            // ---- S = Q K^T (scale folded into Q) ----
            float2 s2[2][2];
            #pragma unroll
            for (int i = 0; i < 2; i++) { s2[i][0] = make_float2(0,0); s2[i][1] = make_float2(0,0); }
            const float* KtB = Kt + buf * 4096;
            #pragma unroll 8
            for (int h = 0; h < 64; h++) {
                float a0 = Qs[(ty*2+0)*64 + h];
                float a1 = Qs[(ty*2+1)*64 + h];
                float2 b0 = *(const float2*)&KtB[h * 64 + tx * 4];
                float2 b1 = *(const float2*)&KtB[h * 64 + tx * 4 + 2];
                float2 A0 = make_float2(a0, a0), A1 = make_float2(a1, a1);
                s2[0][0] = ffma2(A0, b0, s2[0][0]);
                s2[0][1] = ffma2(A0, b1, s2[0][1]);
                s2[1][0] = ffma2(A1, b0, s2[1][0]);
                s2[1][1] = ffma2(A1, b1, s2[1][1]);
            }
            float s[2][4] = {{s2[0][0].x, s2[0][0].y, s2[0][1].x, s2[0][1].y},
                             {s2[1][0].x, s2[1][0].y, s2[1][1].x, s2[1][1].y}};

            if (kt == nkt - 1) {  // diagonal tile mask
                #pragma unroll
                for (int i = 0; i < 2; i++) {
                    int grow = qt * 32 + ty * 2 + i;
                    #pragma unroll
                    for (int j = 0; j < 4; j++)
                        if (kt * 64 + tx * 4 + j > grow) s[i][j] = -INFINITY;
                }
            }

            // ---- online softmax (row reductions over 16 lanes) ----
            #pragma unroll
            for (int i = 0; i < 2; i++) {
                float mt = fmaxf(fmaxf(s[i][0], s[i][1]), fmaxf(s[i][2], s[i][3]));
                #pragma unroll
                for (int o = 8; o >= 1; o >>= 1)
                    mt = fmaxf(mt, __shfl_xor_sync(0xffffffffu, mt, o));
                float mn = fmaxf(m[i], mt);
                float alpha = __expf(m[i] - mn);
                m[i] = mn;
                float p0 = __expf(s[i][0]-mn), p1 = __expf(s[i][1]-mn);
                float p2 = __expf(s[i][2]-mn), p3 = __expf(s[i][3]-mn);
                *(float4*)&Ps[(ty*2+i)*64 + tx*4] = make_float4(p0, p1, p2, p3);
                float rs = (p0 + p1) + (p2 + p3);
                #pragma unroll
                for (int o = 8; o >= 1; o >>= 1)
                    rs += __shfl_xor_sync(0xffffffffu, rs, o);
                l[i] = l[i] * alpha + rs;
                float2 al = make_float2(alpha, alpha);
                acc[i][0] = fmul2(acc[i][0], al);
                acc[i][1] = fmul2(acc[i][1], al);
            }
            __syncwarp();   // Ps rows live entirely within this warp

            // ---- acc += P V ----
            const float* VsB = Vs + buf * 4096;
            #pragma unroll 8
            for (int j = 0; j < 64; j++) {
                float a0 = Ps[(ty*2+0)*64 + j];
                float a1 = Ps[(ty*2+1)*64 + j];
                float4 bv = *(const float4*)&VsB[j * 64 + tx * 4];
                float2 b0 = make_float2(bv.x, bv.y), b1 = make_float2(bv.z, bv.w);
                float2 A0 = make_float2(a0, a0), A1 = make_float2(a1, a1);
                acc[0][0] = ffma2(A0, b0, acc[0][0]);
                acc[0][1] = ffma2(A0, b1, acc[0][1]);
                acc[1][0] = ffma2(A1, b0, acc[1][0]);
                acc[1][1] = ffma2(A1, b1, acc[1][1]);
            }
            __syncwarp();

            __syncthreads();   // all warps done reading buf
            if (pf) {
                float* KtN = Kt + (buf ^ 1) * 4096;
                #pragma unroll
                for (int i = 0; i < 4; i++) {
                    int h0 = (kc4 + i) * 4;
                    KtN[(h0+0)*64 + kr] = kv[i].x;
                    KtN[(h0+1)*64 + kr] = kv[i].y;
                    KtN[(h0+2)*64 + kr] = kv[i].z;
                    KtN[(h0+3)*64 + kr] = kv[i].w;
                }
                cp_wait<0>();
                __syncthreads();   // next buffer ready
            }
        }

        // epilogue
        #pragma unroll
        for (int i = 0; i < 2; i++) {
            float inv = 1.0f / l[i];
            int grow = qt * 32 + ty * 2 + i;
            float4 v = make_float4(acc[i][0].x * inv, acc[i][0].y * inv,
                                   acc[i][1].x * inv, acc[i][1].y * inv);
            *(float4*)(out + ((size_t)b * TT + grow) * HS + tx * 4) = v;
        }
    }
}

// ---------------------------------------------------------------------------
extern "C" void kernel_launch(void* const* d_in, const int* in_sizes, int n_in,
                              void* d_out, int out_size) {
    const float* x  = (const float*)d_in[0];
    const float* Wq = (const float*)d_in[1];
    const float* Wk = (const float*)d_in[2];
    const float* Wv = (const float*)d_in[3];
    float* out = (float*)d_out;

    qkv_kernel<<<ROWS / 64, 256>>>(x, Wq, Wk, Wv);

    size_t smem_bytes = (size_t)(32*64 + 2*64*64 + 2*64*64 + 32*64) * sizeof(float); // 80 KB
    cudaFuncSetAttribute(attn_kernel,
                         cudaFuncAttributeMaxDynamicSharedMemorySize,
                         (int)smem_bytes);
    attn_kernel<<<dim3(32, BB), 256, smem_bytes>>>(out);
}

// round 8
// speedup vs baseline: 1.6543x; 1.3790x over previous
#include <cuda_runtime.h>
#include <cuda_bf16.h>
#include <math.h>
#include <stdint.h>

#define NB 4
#define NT 2048
#define NC 1024
#define NH 64

__device__ float g_q[NB*NT*NH];
__device__ float g_k[NB*NT*NH];
__device__ float g_v[NB*NT*NH];

#define SWZ(o) ((o) ^ (((o) >> 3) & 0x70))

__device__ __forceinline__ uint32_t smem_u32(const void* p) {
    uint32_t a;
    asm("{ .reg .u64 t; cvta.to.shared.u64 t, %1; cvt.u32.u64 %0, t; }" : "=r"(a) : "l"(p));
    return a;
}
// pack two floats to bf16x2: low half = a, high half = b
__device__ __forceinline__ uint32_t cvt2(float a, float b) {
    uint32_t r; asm("cvt.rn.bf16x2.f32 %0, %1, %2;" : "=r"(r) : "f"(b), "f"(a)); return r;
}
// float4 -> hi bf16 pairs + lo (residual) bf16 pairs
__device__ __forceinline__ void split4(float4 v, uint32_t& h01, uint32_t& h23,
                                       uint32_t& l01, uint32_t& l23) {
    h01 = cvt2(v.x, v.y); h23 = cvt2(v.z, v.w);
    float hx = __uint_as_float(h01 << 16), hy = __uint_as_float(h01 & 0xFFFF0000u);
    float hz = __uint_as_float(h23 << 16), hw = __uint_as_float(h23 & 0xFFFF0000u);
    l01 = cvt2(v.x - hx, v.y - hy); l23 = cvt2(v.z - hz, v.w - hw);
}
__device__ __forceinline__ void sts64(uint32_t a, uint32_t x, uint32_t y) {
    asm volatile("st.shared.v2.b32 [%0], {%1,%2};" :: "r"(a), "r"(x), "r"(y));
}
__device__ __forceinline__ void ldm4(uint32_t* r, uint32_t a) {
    asm volatile("ldmatrix.sync.aligned.m8n8.x4.shared.b16 {%0,%1,%2,%3}, [%4];"
        : "=r"(r[0]), "=r"(r[1]), "=r"(r[2]), "=r"(r[3]) : "r"(a));
}
__device__ __forceinline__ void ldm4t(uint32_t* r, uint32_t a) {
    asm volatile("ldmatrix.sync.aligned.m8n8.x4.trans.shared.b16 {%0,%1,%2,%3}, [%4];"
        : "=r"(r[0]), "=r"(r[1]), "=r"(r[2]), "=r"(r[3]) : "r"(a));
}
__device__ __forceinline__ void mma_bf16(float* c, const uint32_t* a, const uint32_t* b) {
    asm volatile("mma.sync.aligned.m16n8k16.row.col.f32.bf16.bf16.f32 "
        "{%0,%1,%2,%3}, {%4,%5,%6,%7}, {%8,%9}, {%10,%11,%12,%13};"
        : "=f"(c[0]), "=f"(c[1]), "=f"(c[2]), "=f"(c[3])
        : "r"(a[0]), "r"(a[1]), "r"(a[2]), "r"(a[3]), "r"(b[0]), "r"(b[1]),
          "f"(c[0]), "f"(c[1]), "f"(c[2]), "f"(c[3]));
}
// A operand (row-major M16xK16, 128B swizzled rows): lanes 0-15 rows, 16-31 k+16B
__device__ __forceinline__ uint32_t addrA(uint32_t base, int row0, int kbyte) {
    int ln = threadIdx.x & 31;
    int row = row0 + (ln & 15), kb = kbyte + (ln >> 4) * 16;
    return base + SWZ((uint32_t)(row * 128 + kb));
}
// B operand from N-major memory ([n][k], k contiguous): pair of n-tiles at n0
__device__ __forceinline__ uint32_t addrB(uint32_t base, int n0, int kbyte) {
    int ln = threadIdx.x & 31;
    int row = n0 + (ln & 7) + ((ln >> 4) << 3);
    int kb = kbyte + ((ln >> 3) & 1) * 16;
    return base + SWZ((uint32_t)(row * 128 + kb));
}
// B operand via trans from K-major memory ([k][n], n contiguous): pair of n-tiles
__device__ __forceinline__ uint32_t addrT(uint32_t base, int k0, int nbyte) {
    int ln = threadIdx.x & 31;
    int row = k0 + (ln & 7) + ((ln >> 3) & 1) * 8;
    int nb = nbyte + (ln >> 4) * 16;
    return base + SWZ((uint32_t)(row * 128 + nb));
}

// ============================================================================
// Kernel 1: QKV. grid 64, block 512 (16 warps: wm=warp>>1 rows, wn=warp&1 cols)
// C tile 128x192, K=1024 in 16 chunks of 64, double buffered.
// ============================================================================
#define QK_XLO 16384
#define QK_W(w) (32768 + (w)*16384)    // hi; lo at +8192
#define QK_BUFSZ 81920
#define QK_SMEM (2*QK_BUFSZ)

__global__ void __launch_bounds__(512, 1) qkv_tc(const float* __restrict__ x,
        const float* __restrict__ Wq, const float* __restrict__ Wk,
        const float* __restrict__ Wv) {
    extern __shared__ char smem[];
    uint32_t sb = smem_u32(smem);
    const int tid = threadIdx.x, lane = tid & 31, warp = tid >> 5;
    const int wm = warp >> 1, wn = warp & 1;
    const int R0 = blockIdx.x * 128;
    const float* Ws[3] = {Wq, Wk, Wv};

    float4 xr[4], wr[6];
    float acc[12][4] = {};

    // ---- LDG chunk -> regs ----
    auto ldg = [&](int chk) {
        const float* xp = x + (size_t)R0 * NC + chk * 64;
        #pragma unroll
        for (int i = 0; i < 4; i++) {
            int idx = tid + i * 512, r = idx >> 4, c4 = idx & 15;
            xr[i] = *(const float4*)(xp + (size_t)r * NC + c4 * 4);
        }
        #pragma unroll
        for (int w = 0; w < 3; w++)
            #pragma unroll
            for (int h = 0; h < 2; h++) {
                int idx = tid + h * 512, r = idx >> 4, c4 = idx & 15;
                wr[w*2+h] = *(const float4*)(Ws[w] + (size_t)(chk*64 + r) * NH + c4 * 4);
            }
    };
    // ---- regs -> smem (split hi/lo, swizzled) ----
    auto sts_all = [&](uint32_t bufb) {
        #pragma unroll
        for (int i = 0; i < 4; i++) {
            int idx = tid + i * 512, r = idx >> 4, c4 = idx & 15;
            uint32_t h01,h23,l01,l23; split4(xr[i], h01,h23,l01,l23);
            uint32_t off = SWZ((uint32_t)(r*128 + c4*8));
            sts64(bufb + off, h01, h23);
            sts64(bufb + QK_XLO + off, l01, l23);
        }
        #pragma unroll
        for (int w = 0; w < 3; w++)
            #pragma unroll
            for (int h = 0; h < 2; h++) {
                int idx = tid + h * 512, r = idx >> 4, c4 = idx & 15;
                uint32_t h01,h23,l01,l23; split4(wr[w*2+h], h01,h23,l01,l23);
                uint32_t off = SWZ((uint32_t)(r*128 + c4*8));
                sts64(bufb + QK_W(w) + off, h01, h23);
                sts64(bufb + QK_W(w) + 8192 + off, l01, l23);
            }
    };

    ldg(0); sts_all(sb); __syncthreads();

    for (int chk = 0; chk < 16; chk++) {
        uint32_t bufb = sb + (uint32_t)(chk & 1) * QK_BUFSZ;
        if (chk + 1 < 16) ldg(chk + 1);

        #pragma unroll
        for (int kk = 0; kk < 4; kk++) {
            uint32_t ah[4], al[4];
            ldm4(ah, addrA(bufb,            wm*16, kk*32));
            ldm4(al, addrA(bufb + QK_XLO,   wm*16, kk*32));
            #pragma unroll
            for (int jp = 0; jp < 6; jp++) {
                int gn = wn * 96 + jp * 16;
                uint32_t wbase = bufb + QK_W(gn >> 6);
                int nb = (gn & 63) * 2;
                uint32_t bh[4], bl[4];
                ldm4t(bh, addrT(wbase,        kk*16, nb));
                ldm4t(bl, addrT(wbase + 8192, kk*16, nb));
                mma_bf16(acc[2*jp],   ah, bh);
                mma_bf16(acc[2*jp+1], ah, bh + 2);
                mma_bf16(acc[2*jp],   ah, bl);
                mma_bf16(acc[2*jp+1], ah, bl + 2);
                mma_bf16(acc[2*jp],   al, bh);
                mma_bf16(acc[2*jp+1], al, bh + 2);
            }
        }
        if (chk + 1 < 16) sts_all(sb + (uint32_t)((chk+1) & 1) * QK_BUFSZ);
        __syncthreads();
    }

    float* outs[3] = {g_q, g_k, g_v};
    int r0 = R0 + wm*16 + (lane >> 2);
    #pragma unroll
    for (int j = 0; j < 12; j++) {
        int gn = wn*96 + j*8 + 2*(lane & 3);
        float* o = outs[gn >> 6] + (size_t)r0 * NH + (gn & 63);
        *(float2*)o            = make_float2(acc[j][0], acc[j][1]);
        *(float2*)(o + 8*NH)   = make_float2(acc[j][2], acc[j][3]);
    }
}

// ============================================================================
// Kernel 2: causal attention. grid (16,4), block 256 (8 warps x 16 rows).
// M=128, BN=64, no max subtraction, P stays in registers (S-frag -> A-frag).
// ============================================================================
#define AT_QLO 16384
#define AT_KV(bu) (32768u + (bu)*32768u)   // KHI+0 KLO+8192 VHI+16384 VLO+24576
#define AT_SMEM (32768 + 2*32768)

__global__ void __launch_bounds__(256, 1) attn_tc(float* __restrict__ out) {
    extern __shared__ char smem[];
    uint32_t sb = smem_u32(smem);
    const int tid = threadIdx.x, lane = tid & 31, warp = tid >> 5;
    const int qt = blockIdx.x, b = blockIdx.y;
    const int nkt = 2*qt + 2;
    const float scale = 0.03125f;   // 1/sqrt(C)

    const float* qb = g_q + ((size_t)b * NT + (size_t)qt * 128) * NH;
    const float* kb = g_k + (size_t)b * NT * NH;
    const float* vb = g_v + (size_t)b * NT * NH;

    // stage Q (pre-scaled)
    #pragma unroll
    for (int i = 0; i < 8; i++) {
        int idx = tid + i * 256, r = idx >> 4, c4 = idx & 15;
        float4 v = *(const float4*)(qb + (size_t)r * NH + c4 * 4);
        v.x *= scale; v.y *= scale; v.z *= scale; v.w *= scale;
        uint32_t h01,h23,l01,l23; split4(v, h01,h23,l01,l23);
        uint32_t off = SWZ((uint32_t)(r*128 + c4*8));
        sts64(sb + off, h01, h23);
        sts64(sb + AT_QLO + off, l01, l23);
    }
    // stage KV tile 0
    float4 kreg[4], vreg[4];
    #pragma unroll
    for (int i = 0; i < 4; i++) {
        int idx = tid + i * 256, r = idx >> 4, c4 = idx & 15;
        kreg[i] = *(const float4*)(kb + (size_t)r * NH + c4 * 4);
        vreg[i] = *(const float4*)(vb + (size_t)r * NH + c4 * 4);
    }
    #pragma unroll
    for (int i = 0; i < 4; i++) {
        int idx = tid + i * 256, r = idx >> 4, c4 = idx & 15;
        uint32_t off = SWZ((uint32_t)(r*128 + c4*8));
        uint32_t h01,h23,l01,l23;
        split4(kreg[i], h01,h23,l01,l23);
        sts64(sb + AT_KV(0) + off, h01, h23);
        sts64(sb + AT_KV(0) + 8192 + off, l01, l23);
        split4(vreg[i], h01,h23,l01,l23);
        sts64(sb + AT_KV(0) + 16384 + off, h01, h23);
        sts64(sb + AT_KV(0) + 24576 + off, l01, l23);
    }
    __syncthreads();

    // Q fragments (held in regs all loop)
    uint32_t qh[4][4], ql[4][4];
    #pragma unroll
    for (int kk = 0; kk < 4; kk++) {
        ldm4(qh[kk], addrA(sb,           warp*16, kk*32));
        ldm4(ql[kk], addrA(sb + AT_QLO,  warp*16, kk*32));
    }

    float o[8][4] = {};
    float l0 = 0.f, l1 = 0.f;
    const int rowA = qt*128 + warp*16 + (lane >> 2);
    const int rowB = rowA + 8;

    for (int kt = 0; kt < nkt; kt++) {
        uint32_t kvb = sb + AT_KV(kt & 1);
        bool pf = (kt + 1 < nkt);
        if (pf) {
            const float* kp = kb + (size_t)(kt+1) * 64 * NH;
            const float* vp = vb + (size_t)(kt+1) * 64 * NH;
            #pragma unroll
            for (int i = 0; i < 4; i++) {
                int idx = tid + i * 256, r = idx >> 4, c4 = idx & 15;
                kreg[i] = *(const float4*)(kp + (size_t)r * NH + c4 * 4);
                vreg[i] = *(const float4*)(vp + (size_t)r * NH + c4 * 4);
            }
        }

        // ---- S = Q K^T ----
        float s[8][4] = {};
        #pragma unroll
        for (int kk = 0; kk < 4; kk++) {
            uint32_t bh[16], bl[16];
            #pragma unroll
            for (int jp = 0; jp < 4; jp++) {
                ldm4(bh + jp*4, addrB(kvb,        jp*16, kk*32));
                ldm4(bl + jp*4, addrB(kvb + 8192, jp*16, kk*32));
            }
            #pragma unroll
            for (int j = 0; j < 8; j++) {
                mma_bf16(s[j], qh[kk], bh + j*2);
                mma_bf16(s[j], qh[kk], bl + j*2);
                mma_bf16(s[j], ql[kk], bh + j*2);
            }
        }

        // ---- exp + row-sum + pack P into PV A-fragments (registers only) ----
        uint32_t pah[4][4], pal[4][4];
        bool domask = (kt*64 + 63 > qt*128 + warp*16);
        #pragma unroll
        for (int j = 0; j < 8; j++) {
            int col = kt*64 + j*8 + 2*(lane & 3);
            float p0, p1, p2, p3;
            if (domask) {
                p0 = (col     <= rowA) ? __expf(s[j][0]) : 0.f;
                p1 = (col + 1 <= rowA) ? __expf(s[j][1]) : 0.f;
                p2 = (col     <= rowB) ? __expf(s[j][2]) : 0.f;
                p3 = (col + 1 <= rowB) ? __expf(s[j][3]) : 0.f;
            } else {
                p0 = __expf(s[j][0]); p1 = __expf(s[j][1]);
                p2 = __expf(s[j][2]); p3 = __expf(s[j][3]);
            }
            l0 += p0 + p1; l1 += p2 + p3;
            uint32_t h01 = cvt2(p0, p1), h23 = cvt2(p2, p3);
            uint32_t q01 = cvt2(p0 - __uint_as_float(h01 << 16),
                                p1 - __uint_as_float(h01 & 0xFFFF0000u));
            uint32_t q23 = cvt2(p2 - __uint_as_float(h23 << 16),
                                p3 - __uint_as_float(h23 & 0xFFFF0000u));
            pah[j >> 1][(j & 1)*2]     = h01;
            pah[j >> 1][(j & 1)*2 + 1] = h23;
            pal[j >> 1][(j & 1)*2]     = q01;
            pal[j >> 1][(j & 1)*2 + 1] = q23;
        }

        // ---- O += P V ----
        #pragma unroll
        for (int kk = 0; kk < 4; kk++) {
            uint32_t vh[16], vl[16];
            #pragma unroll
            for (int jp = 0; jp < 4; jp++) {
                ldm4t(vh + jp*4, addrT(kvb + 16384, kk*16, jp*32));
                ldm4t(vl + jp*4, addrT(kvb + 24576, kk*16, jp*32));
            }
            #pragma unroll
            for (int j = 0; j < 8; j++) {
                mma_bf16(o[j], pah[kk], vh + j*2);
                mma_bf16(o[j], pah[kk], vl + j*2);
                mma_bf16(o[j], pal[kk], vh + j*2);
            }
        }

        // ---- STS next tile into other buffer ----
        if (pf) {
            uint32_t nb2 = sb + AT_KV((kt + 1) & 1);
            #pragma unroll
            for (int i = 0; i < 4; i++) {
                int idx = tid + i * 256, r = idx >> 4, c4 = idx & 15;
                uint32_t off = SWZ((uint32_t)(r*128 + c4*8));
                uint32_t h01,h23,l01,l23;
                split4(kreg[i], h01,h23,l01,l23);
                sts64(nb2 + off, h01, h23);
                sts64(nb2 + 8192 + off, l01, l23);
                split4(vreg[i], h01,h23,l01,l23);
                sts64(nb2 + 16384 + off, h01, h23);
                sts64(nb2 + 24576 + off, l01, l23);
            }
        }
        __syncthreads();
    }

    // ---- epilogue: row sums via quad shuffle, normalize, store ----
    l0 += __shfl_xor_sync(0xffffffffu, l0, 1);
    l0 += __shfl_xor_sync(0xffffffffu, l0, 2);
    l1 += __shfl_xor_sync(0xffffffffu, l1, 1);
    l1 += __shfl_xor_sync(0xffffffffu, l1, 2);
    float i0 = 1.0f / l0, i1 = 1.0f / l1;

    float* ob = out + ((size_t)b * NT + rowA) * NH;
    #pragma unroll
    for (int j = 0; j < 8; j++) {
        int col = j*8 + 2*(lane & 3);
        *(float2*)(ob + col)          = make_float2(o[j][0]*i0, o[j][1]*i0);
        *(float2*)(ob + 8*NH + col)   = make_float2(o[j][2]*i1, o[j][3]*i1);
    }
}

// ---------------------------------------------------------------------------
extern "C" void kernel_launch(void* const* d_in, const int* in_sizes, int n_in,
                              void* d_out, int out_size) {
    const float* x  = (const float*)d_in[0];
    const float* Wq = (const float*)d_in[1];
    const float* Wk = (const float*)d_in[2];
    const float* Wv = (const float*)d_in[3];
    float* out = (float*)d_out;

    cudaFuncSetAttribute(qkv_tc, cudaFuncAttributeMaxDynamicSharedMemorySize, QK_SMEM);
    qkv_tc<<<64, 512, QK_SMEM>>>(x, Wq, Wk, Wv);

    cudaFuncSetAttribute(attn_tc, cudaFuncAttributeMaxDynamicSharedMemorySize, AT_SMEM);
    attn_tc<<<dim3(16, NB), 256, AT_SMEM>>>(out);
}

// round 10
// speedup vs baseline: 2.9929x; 1.8091x over previous
#include <cuda_runtime.h>
#include <cuda_bf16.h>
#include <math.h>
#include <stdint.h>

#define NB 4
#define NT 2048
#define NC 1024
#define NH 64

__device__ float g_q[NB*NT*NH];
__device__ float g_k[NB*NT*NH];
__device__ float g_v[NB*NT*NH];
// split-K attention partials: 40 units/batch * 4 batches
__device__ float g_po[160*128*64];
__device__ float g_pl[160*128];

// unit tables (descending qt => big units scheduled in wave 1)
__constant__ uint8_t c_qt[40] = {15,15,15,15,14,14,14,14,13,13,13,13,12,12,12,12,
                                 11,11,11,10,10,10,9,9,9,8,8,8,7,7,6,6,5,5,4,4,3,2,1,0};
__constant__ uint8_t c_sp[40] = {0,1,2,3,0,1,2,3,0,1,2,3,0,1,2,3,
                                 0,1,2,0,1,2,0,1,2,0,1,2,0,1,0,1,0,1,0,1,0,0,0,0};
__constant__ uint8_t c_cnt[16] = {1,1,1,1,2,2,2,2,3,3,3,3,4,4,4,4};
__constant__ uint8_t c_cb[16]  = {39,38,37,36,34,32,30,28,25,22,19,16,12,8,4,0};

#define SWZ(o) ((o) ^ (((o) >> 3) & 0x70))

__device__ __forceinline__ uint32_t smem_u32(const void* p) {
    uint32_t a;
    asm("{ .reg .u64 t; cvta.to.shared.u64 t, %1; cvt.u32.u64 %0, t; }" : "=r"(a) : "l"(p));
    return a;
}
__device__ __forceinline__ uint32_t cvt2(float a, float b) {
    uint32_t r; asm("cvt.rn.bf16x2.f32 %0, %1, %2;" : "=r"(r) : "f"(b), "f"(a)); return r;
}
__device__ __forceinline__ void split4(float4 v, uint32_t& h01, uint32_t& h23,
                                       uint32_t& l01, uint32_t& l23) {
    h01 = cvt2(v.x, v.y); h23 = cvt2(v.z, v.w);
    float hx = __uint_as_float(h01 << 16), hy = __uint_as_float(h01 & 0xFFFF0000u);
    float hz = __uint_as_float(h23 << 16), hw = __uint_as_float(h23 & 0xFFFF0000u);
    l01 = cvt2(v.x - hx, v.y - hy); l23 = cvt2(v.z - hz, v.w - hw);
}
__device__ __forceinline__ void sts64(uint32_t a, uint32_t x, uint32_t y) {
    asm volatile("st.shared.v2.b32 [%0], {%1,%2};" :: "r"(a), "r"(x), "r"(y));
}
__device__ __forceinline__ void ldm4(uint32_t* r, uint32_t a) {
    asm volatile("ldmatrix.sync.aligned.m8n8.x4.shared.b16 {%0,%1,%2,%3}, [%4];"
        : "=r"(r[0]), "=r"(r[1]), "=r"(r[2]), "=r"(r[3]) : "r"(a));
}
__device__ __forceinline__ void ldm4t(uint32_t* r, uint32_t a) {
    asm volatile("ldmatrix.sync.aligned.m8n8.x4.trans.shared.b16 {%0,%1,%2,%3}, [%4];"
        : "=r"(r[0]), "=r"(r[1]), "=r"(r[2]), "=r"(r[3]) : "r"(a));
}
__device__ __forceinline__ void mma_bf16(float* c, const uint32_t* a, const uint32_t* b) {
    asm volatile("mma.sync.aligned.m16n8k16.row.col.f32.bf16.bf16.f32 "
        "{%0,%1,%2,%3}, {%4,%5,%6,%7}, {%8,%9}, {%10,%11,%12,%13};"
        : "=f"(c[0]), "=f"(c[1]), "=f"(c[2]), "=f"(c[3])
        : "r"(a[0]), "r"(a[1]), "r"(a[2]), "r"(a[3]), "r"(b[0]), "r"(b[1]),
          "f"(c[0]), "f"(c[1]), "f"(c[2]), "f"(c[3]));
}
__device__ __forceinline__ uint32_t addrA(uint32_t base, int row0, int kbyte) {
    int ln = threadIdx.x & 31;
    int row = row0 + (ln & 15), kb = kbyte + (ln >> 4) * 16;
    return base + SWZ((uint32_t)(row * 128 + kb));
}
__device__ __forceinline__ uint32_t addrB(uint32_t base, int n0, int kbyte) {
    int ln = threadIdx.x & 31;
    int row = n0 + (ln & 7) + ((ln >> 4) << 3);
    int kb = kbyte + ((ln >> 3) & 1) * 16;
    return base + SWZ((uint32_t)(row * 128 + kb));
}
__device__ __forceinline__ uint32_t addrT(uint32_t base, int k0, int nbyte) {
    int ln = threadIdx.x & 31;
    int row = k0 + (ln & 7) + ((ln >> 3) & 1) * 8;
    int nb = nbyte + (ln >> 4) * 16;
    return base + SWZ((uint32_t)(row * 128 + nb));
}

// ============================================================================
// Kernel 1: QKV. grid 128 (M=64 row tiles), block 512 (16 warps: 4 wm x 4 wn).
// C tile 64x192, K=1024 in 16 chunks of 64, double buffered.
// ============================================================================
#define QK_XLO 8192
#define QK_W(w) (16384 + (w)*16384)   // hi; lo at +8192
#define QK_BUFSZ 65536
#define QK_SMEM (2*QK_BUFSZ)          // 128 KB

__global__ void __launch_bounds__(512, 1) qkv_tc(const float* __restrict__ x,
        const float* __restrict__ Wq, const float* __restrict__ Wk,
        const float* __restrict__ Wv) {
    extern __shared__ char smem[];
    uint32_t sb = smem_u32(smem);
    const int tid = threadIdx.x, lane = tid & 31, warp = tid >> 5;
    const int wm = warp >> 2, wn = warp & 3;     // 4 row strips x 4 col groups
    const int R0 = blockIdx.x * 64;
    const float* Ws[3] = {Wq, Wk, Wv};

    float4 xr[2], wr[6];
    float acc[6][4] = {};

    auto ldg = [&](int chk) {
        const float* xp = x + (size_t)R0 * NC + chk * 64;
        #pragma unroll
        for (int i = 0; i < 2; i++) {
            int idx = tid + i * 512, r = idx >> 4, c4 = idx & 15;
            xr[i] = *(const float4*)(xp + (size_t)r * NC + c4 * 4);
        }
        #pragma unroll
        for (int w = 0; w < 3; w++)
            #pragma unroll
            for (int h = 0; h < 2; h++) {
                int idx = tid + h * 512, r = idx >> 4, c4 = idx & 15;
                wr[w*2+h] = *(const float4*)(Ws[w] + (size_t)(chk*64 + r) * NH + c4 * 4);
            }
    };
    auto sts_all = [&](uint32_t bufb) {
        #pragma unroll
        for (int i = 0; i < 2; i++) {
            int idx = tid + i * 512, r = idx >> 4, c4 = idx & 15;
            uint32_t h01,h23,l01,l23; split4(xr[i], h01,h23,l01,l23);
            uint32_t off = SWZ((uint32_t)(r*128 + c4*8));
            sts64(bufb + off, h01, h23);
            sts64(bufb + QK_XLO + off, l01, l23);
        }
        #pragma unroll
        for (int w = 0; w < 3; w++)
            #pragma unroll
            for (int h = 0; h < 2; h++) {
                int idx = tid + h * 512, r = idx >> 4, c4 = idx & 15;
                uint32_t h01,h23,l01,l23; split4(wr[w*2+h], h01,h23,l01,l23);
                uint32_t off = SWZ((uint32_t)(r*128 + c4*8));
                sts64(bufb + QK_W(w) + off, h01, h23);
                sts64(bufb + QK_W(w) + 8192 + off, l01, l23);
            }
    };

    ldg(0); sts_all(sb); __syncthreads();

    for (int chk = 0; chk < 16; chk++) {
        uint32_t bufb = sb + (uint32_t)(chk & 1) * QK_BUFSZ;
        if (chk + 1 < 16) ldg(chk + 1);

        #pragma unroll
        for (int kk = 0; kk < 4; kk++) {
            uint32_t ah[4], al[4];
            ldm4(ah, addrA(bufb,           wm*16, kk*32));
            ldm4(al, addrA(bufb + QK_XLO,  wm*16, kk*32));
            #pragma unroll
            for (int jp = 0; jp < 3; jp++) {
                int gn = wn * 48 + jp * 16;
                uint32_t wb = bufb + QK_W(gn >> 6);
                int nb = (gn & 63) * 2;
                uint32_t bh[4], bl[4];
                ldm4t(bh, addrT(wb,        kk*16, nb));
                ldm4t(bl, addrT(wb + 8192, kk*16, nb));
                mma_bf16(acc[2*jp],   ah, bh);
                mma_bf16(acc[2*jp+1], ah, bh + 2);
                mma_bf16(acc[2*jp],   ah, bl);
                mma_bf16(acc[2*jp+1], ah, bl + 2);
                mma_bf16(acc[2*jp],   al, bh);
                mma_bf16(acc[2*jp+1], al, bh + 2);
            }
        }
        if (chk + 1 < 16) sts_all(sb + (uint32_t)((chk+1) & 1) * QK_BUFSZ);
        __syncthreads();
    }

    float* outs[3] = {g_q, g_k, g_v};
    int r0 = R0 + wm*16 + (lane >> 2);
    #pragma unroll
    for (int jp = 0; jp < 3; jp++)
        #pragma unroll
        for (int h = 0; h < 2; h++) {
            int gn = wn*48 + jp*16 + h*8 + 2*(lane & 3);
            float* o = outs[gn >> 6] + (size_t)r0 * NH + (gn & 63);
            *(float2*)o          = make_float2(acc[jp*2+h][0], acc[jp*2+h][1]);
            *(float2*)(o + 8*NH) = make_float2(acc[jp*2+h][2], acc[jp*2+h][3]);
        }
}

// ============================================================================
// Kernel 2: causal attention, split-K. grid (40,4), block 256 (8 warps).
// Unit c = (qt, split): k-tiles [k0,k1), <=8 iters. Writes unnormalized
// partial O + row sums l to scratch (linear combine: no max subtraction).
// ============================================================================
#define AT_QLO 16384
#define AT_KV(bu) (32768u + (bu)*32768u)   // KHI+0 KLO+8192 VHI+16384 VLO+24576
#define AT_SMEM (32768 + 2*32768)

__global__ void __launch_bounds__(256, 1) attn_tc() {
    extern __shared__ char smem[];
    uint32_t sb = smem_u32(smem);
    const int tid = threadIdx.x, lane = tid & 31, warp = tid >> 5;
    const int c = blockIdx.x, b = blockIdx.y;
    const int qt = c_qt[c], sp = c_sp[c];
    const int cnt = c_cnt[qt];
    const int nk = 2*qt + 2;
    const int per = (nk + cnt - 1) / cnt;
    const int k0 = sp * per;
    const int k1 = (k0 + per < nk) ? (k0 + per) : nk;
    const float scale = 0.03125f;

    const float* qb = g_q + ((size_t)b * NT + (size_t)qt * 128) * NH;
    const float* kb = g_k + (size_t)b * NT * NH;
    const float* vb = g_v + (size_t)b * NT * NH;

    // stage Q (pre-scaled)
    #pragma unroll
    for (int i = 0; i < 8; i++) {
        int idx = tid + i * 256, r = idx >> 4, c4 = idx & 15;
        float4 v = *(const float4*)(qb + (size_t)r * NH + c4 * 4);
        v.x *= scale; v.y *= scale; v.z *= scale; v.w *= scale;
        uint32_t h01,h23,l01,l23; split4(v, h01,h23,l01,l23);
        uint32_t off = SWZ((uint32_t)(r*128 + c4*8));
        sts64(sb + off, h01, h23);
        sts64(sb + AT_QLO + off, l01, l23);
    }
    // stage KV tile k0
    float4 kreg[4], vreg[4];
    {
        const float* kp = kb + (size_t)k0 * 64 * NH;
        const float* vp = vb + (size_t)k0 * 64 * NH;
        #pragma unroll
        for (int i = 0; i < 4; i++) {
            int idx = tid + i * 256, r = idx >> 4, c4 = idx & 15;
            kreg[i] = *(const float4*)(kp + (size_t)r * NH + c4 * 4);
            vreg[i] = *(const float4*)(vp + (size_t)r * NH + c4 * 4);
        }
        #pragma unroll
        for (int i = 0; i < 4; i++) {
            int idx = tid + i * 256, r = idx >> 4, c4 = idx & 15;
            uint32_t off = SWZ((uint32_t)(r*128 + c4*8));
            uint32_t h01,h23,l01,l23;
            split4(kreg[i], h01,h23,l01,l23);
            sts64(sb + AT_KV(0) + off, h01, h23);
            sts64(sb + AT_KV(0) + 8192 + off, l01, l23);
            split4(vreg[i], h01,h23,l01,l23);
            sts64(sb + AT_KV(0) + 16384 + off, h01, h23);
            sts64(sb + AT_KV(0) + 24576 + off, l01, l23);
        }
    }
    __syncthreads();

    uint32_t qh[4][4], ql[4][4];
    #pragma unroll
    for (int kk = 0; kk < 4; kk++) {
        ldm4(qh[kk], addrA(sb,          warp*16, kk*32));
        ldm4(ql[kk], addrA(sb + AT_QLO, warp*16, kk*32));
    }

    float o[8][4] = {};
    float l0 = 0.f, l1 = 0.f;
    const int lr   = warp*16 + (lane >> 2);
    const int rowA = qt*128 + lr;
    const int rowB = rowA + 8;

    for (int kt = k0; kt < k1; kt++) {
        const int it = kt - k0;
        uint32_t kvb = sb + AT_KV(it & 1);
        bool pf = (kt + 1 < k1);
        if (pf) {
            const float* kp = kb + (size_t)(kt+1) * 64 * NH;
            const float* vp = vb + (size_t)(kt+1) * 64 * NH;
            #pragma unroll
            for (int i = 0; i < 4; i++) {
                int idx = tid + i * 256, r = idx >> 4, c4 = idx & 15;
                kreg[i] = *(const float4*)(kp + (size_t)r * NH + c4 * 4);
                vreg[i] = *(const float4*)(vp + (size_t)r * NH + c4 * 4);
            }
        }

        // S = Q K^T
        float s[8][4] = {};
        #pragma unroll
        for (int kk = 0; kk < 4; kk++) {
            uint32_t bh[16], bl[16];
            #pragma unroll
            for (int jp = 0; jp < 4; jp++) {
                ldm4(bh + jp*4, addrB(kvb,        jp*16, kk*32));
                ldm4(bl + jp*4, addrB(kvb + 8192, jp*16, kk*32));
            }
            #pragma unroll
            for (int j = 0; j < 8; j++) {
                mma_bf16(s[j], qh[kk], bh + j*2);
                mma_bf16(s[j], qh[kk], bl + j*2);
                mma_bf16(s[j], ql[kk], bh + j*2);
            }
        }

        // exp + row-sum + pack P A-fragments (registers only)
        uint32_t pah[4][4], pal[4][4];
        bool domask = (kt*64 + 63 > qt*128 + warp*16);
        #pragma unroll
        for (int j = 0; j < 8; j++) {
            int col = kt*64 + j*8 + 2*(lane & 3);
            float p0, p1, p2, p3;
            if (domask) {
                p0 = (col     <= rowA) ? __expf(s[j][0]) : 0.f;
                p1 = (col + 1 <= rowA) ? __expf(s[j][1]) : 0.f;
                p2 = (col     <= rowB) ? __expf(s[j][2]) : 0.f;
                p3 = (col + 1 <= rowB) ? __expf(s[j][3]) : 0.f;
            } else {
                p0 = __expf(s[j][0]); p1 = __expf(s[j][1]);
                p2 = __expf(s[j][2]); p3 = __expf(s[j][3]);
            }
            l0 += p0 + p1; l1 += p2 + p3;
            uint32_t h01 = cvt2(p0, p1), h23 = cvt2(p2, p3);
            uint32_t q01 = cvt2(p0 - __uint_as_float(h01 << 16),
                                p1 - __uint_as_float(h01 & 0xFFFF0000u));
            uint32_t q23 = cvt2(p2 - __uint_as_float(h23 << 16),
                                p3 - __uint_as_float(h23 & 0xFFFF0000u));
            pah[j >> 1][(j & 1)*2]     = h01;
            pah[j >> 1][(j & 1)*2 + 1] = h23;
            pal[j >> 1][(j & 1)*2]     = q01;
            pal[j >> 1][(j & 1)*2 + 1] = q23;
        }

        // O += P V
        #pragma unroll
        for (int kk = 0; kk < 4; kk++) {
            uint32_t vh[16], vl[16];
            #pragma unroll
            for (int jp = 0; jp < 4; jp++) {
                ldm4t(vh + jp*4, addrT(kvb + 16384, kk*16, jp*32));
                ldm4t(vl + jp*4, addrT(kvb + 24576, kk*16, jp*32));
            }
            #pragma unroll
            for (int j = 0; j < 8; j++) {
                mma_bf16(o[j], pah[kk], vh + j*2);
                mma_bf16(o[j], pah[kk], vl + j*2);
                mma_bf16(o[j], pal[kk], vh + j*2);
            }
        }

        if (pf) {
            uint32_t nb2 = sb + AT_KV((it + 1) & 1);
            #pragma unroll
            for (int i = 0; i < 4; i++) {
                int idx = tid + i * 256, r = idx >> 4, c4 = idx & 15;
                uint32_t off = SWZ((uint32_t)(r*128 + c4*8));
                uint32_t h01,h23,l01,l23;
                split4(kreg[i], h01,h23,l01,l23);
                sts64(nb2 + off, h01, h23);
                sts64(nb2 + 8192 + off, l01, l23);
                split4(vreg[i], h01,h23,l01,l23);
                sts64(nb2 + 16384 + off, h01, h23);
                sts64(nb2 + 24576 + off, l01, l23);
            }
        }
        __syncthreads();
    }

    // epilogue: quad-reduce row sums; write partial O + l to scratch
    l0 += __shfl_xor_sync(0xffffffffu, l0, 1);
    l0 += __shfl_xor_sync(0xffffffffu, l0, 2);
    l1 += __shfl_xor_sync(0xffffffffu, l1, 1);
    l1 += __shfl_xor_sync(0xffffffffu, l1, 2);

    const uint32_t u = (uint32_t)b * 40 + c;
    if ((lane & 3) == 0) {
        g_pl[u*128 + lr]     = l0;
        g_pl[u*128 + lr + 8] = l1;
    }
    float* pb = g_po + (size_t)u * 8192 + (size_t)lr * 64;
    #pragma unroll
    for (int j = 0; j < 8; j++) {
        int col = j*8 + 2*(lane & 3);
        *(float2*)(pb + col)          = make_float2(o[j][0], o[j][1]);
        *(float2*)(pb + 8*64 + col)   = make_float2(o[j][2], o[j][3]);
    }
}

// ============================================================================
// Kernel 3: combine partials. grid (16,4), block 256.
// out[b, qt*128+row, :] = sum_splits O_p / sum_splits l_p
// ============================================================================
__global__ void __launch_bounds__(256) combine(float* __restrict__ out) {
    const int qt = blockIdx.x, b = blockIdx.y;
    const int cnt = c_cnt[qt], cb = c_cb[qt];
    const int tid = threadIdx.x;
    __shared__ float ls[128];

    if (tid < 128) {
        float s = 0.f;
        for (int i = 0; i < cnt; i++)
            s += g_pl[((uint32_t)b*40 + cb + i)*128 + tid];
        ls[tid] = s;
    }
    __syncthreads();

    const int row = tid >> 1, col0 = (tid & 1) * 32;
    float4 acc[8] = {};
    for (int i = 0; i < cnt; i++) {
        const float* pb = g_po + (size_t)((uint32_t)b*40 + cb + i) * 8192
                        + (size_t)row * 64 + col0;
        #pragma unroll
        for (int j = 0; j < 8; j++) {
            float4 v = *(const float4*)(pb + j*4);
            acc[j].x += v.x; acc[j].y += v.y; acc[j].z += v.z; acc[j].w += v.w;
        }
    }
    float inv = 1.0f / ls[row];
    float* ob = out + ((size_t)b * NT + (size_t)qt * 128 + row) * NH + col0;
    #pragma unroll
    for (int j = 0; j < 8; j++) {
        float4 v = make_float4(acc[j].x*inv, acc[j].y*inv, acc[j].z*inv, acc[j].w*inv);
        *(float4*)(ob + j*4) = v;
    }
}

// ---------------------------------------------------------------------------
extern "C" void kernel_launch(void* const* d_in, const int* in_sizes, int n_in,
                              void* d_out, int out_size) {
    const float* x  = (const float*)d_in[0];
    const float* Wq = (const float*)d_in[1];
    const float* Wk = (const float*)d_in[2];
    const float* Wv = (const float*)d_in[3];
    float* out = (float*)d_out;

    cudaFuncSetAttribute(qkv_tc, cudaFuncAttributeMaxDynamicSharedMemorySize, QK_SMEM);
    qkv_tc<<<128, 512, QK_SMEM>>>(x, Wq, Wk, Wv);

    cudaFuncSetAttribute(attn_tc, cudaFuncAttributeMaxDynamicSharedMemorySize, AT_SMEM);
    attn_tc<<<dim3(40, NB), 256, AT_SMEM>>>();

    combine<<<dim3(16, NB), 256>>>(out);
}